// round 15
// baseline (speedup 1.0000x reference)
#include <cuda_runtime.h>
#include <cuda_bf16.h>
#include <cstdint>

// MXIntGELU: out = mxint_quant(relu(x)) with block (1,32) shared exponent.
//
// GELU reduces exactly to relu (clipped==0 => poly==1 => L=sign(x));
// input quantization is dead code. Per 32 contiguous elements v>=0:
//   e = floor(log2(max(blockmax, 2^-126)))  [fp32 exponent field, exact]
//   out = min(rint(v*2^(6-e)), 127) * 2^(e-6)
//
// R8 measured: 82.2us, DRAM 81.1%, regs=32 -> ptxas serialized the 4 loads.
// R9-R12 (unmeasured, broker timeouts): guard-free exact-shape kernel.
// R13-R15: same lever, enforced — the 4 streaming loads are back-to-back
// asm volatile ld.global.cs.v4.f32, which ptxas cannot reorder or sink,
// guaranteeing front-of-body MLP=4 instead of relying on scheduling mood.

__device__ __forceinline__ float4 ldcs_v4(const float4* p)
{
    float4 v;
    asm volatile("ld.global.cs.v4.f32 {%0,%1,%2,%3}, [%4];"
                 : "=f"(v.x), "=f"(v.y), "=f"(v.z), "=f"(v.w)
                 : "l"(p));
    return v;
}

__device__ __forceinline__ void stcs_v4(float4* p, float4 v)
{
    asm volatile("st.global.cs.v4.f32 [%0], {%1,%2,%3,%4};"
                 :: "l"(p), "f"(v.x), "f"(v.y), "f"(v.z), "f"(v.w)
                 : "memory");
}

__device__ __forceinline__ float4 quant_block(float4 x)
{
    float v0 = fmaxf(x.x, 0.0f);
    float v1 = fmaxf(x.y, 0.0f);
    float v2 = fmaxf(x.z, 0.0f);
    float v3 = fmaxf(x.w, 0.0f);

    // 32-elem block max across the 8-lane group
    float m = fmaxf(fmaxf(v0, v1), fmaxf(v2, v3));
    m = fmaxf(m, __shfl_xor_sync(0xffffffffu, m, 1));
    m = fmaxf(m, __shfl_xor_sync(0xffffffffu, m, 2));
    m = fmaxf(m, __shfl_xor_sync(0xffffffffu, m, 4));

    // e = floor(log2(max(m, 2^-126))) via exponent field (exact for normals)
    m = fmaxf(m, 1.1754943508222875e-38f);   // 2^-126
    int e = (__float_as_int(m) >> 23) - 127;

    int es = e - 6; if (es < -126) es = -126;
    int ei = 6 - e; if (ei >  127) ei =  127;
    float scale = __int_as_float((es + 127) << 23);
    float inv   = __int_as_float((ei + 127) << 23);

    // v*inv in [0,128); rint can hit 128 on the block max -> clamp 127.
    // rintf = round-half-to-even = jnp.round. v>=0 so no low clamp.
    float4 r;
    r.x = fminf(rintf(v0 * inv), 127.0f) * scale;
    r.y = fminf(rintf(v1 * inv), 127.0f) * scale;
    r.z = fminf(rintf(v2 * inv), 127.0f) * scale;
    r.w = fminf(rintf(v3 * inv), 127.0f) * scale;
    return r;
}

// Exact-shape kernel: grid*block == q4, n4 == 4*q4. No guards; the four
// volatile-asm loads are emitted consecutively -> guaranteed MLP_p1=4.
__global__ void __launch_bounds__(256)
mxint_gelu_exact(const float4* __restrict__ in,
                 float4* __restrict__ out,
                 int q4)
{
    int i = blockIdx.x * 256 + threadIdx.x;
    int i1 = i + q4;
    int i2 = i + 2 * q4;
    int i3 = i + 3 * q4;

    float4 a = ldcs_v4(&in[i]);
    float4 b = ldcs_v4(&in[i1]);
    float4 c = ldcs_v4(&in[i2]);
    float4 d = ldcs_v4(&in[i3]);

    float4 ra = quant_block(a);
    float4 rb = quant_block(b);
    float4 rc = quant_block(c);
    float4 rd = quant_block(d);

    stcs_v4(&out[i],  ra);
    stcs_v4(&out[i1], rb);
    stcs_v4(&out[i2], rc);
    stcs_v4(&out[i3], rd);
}

// General fallback (any n divisible by 32); plain intrinsics, never taken
// for the benchmark shape.
__global__ void __launch_bounds__(256)
mxint_gelu_guarded(const float4* __restrict__ in,
                   float4* __restrict__ out,
                   int n4, int q4)
{
    int i = blockIdx.x * blockDim.x + threadIdx.x;
    if (i >= q4) return;
    int i1 = i + q4;
    int i2 = i + 2 * q4;
    int i3 = i + 3 * q4;

    const float4 z = make_float4(0.f, 0.f, 0.f, 0.f);
    float4 a = __ldcs(&in[i]);
    float4 b = (i1 < n4) ? __ldcs(&in[i1]) : z;
    float4 c = (i2 < n4) ? __ldcs(&in[i2]) : z;
    float4 d = (i3 < n4) ? __ldcs(&in[i3]) : z;

    float4 ra = quant_block(a);
    float4 rb = quant_block(b);
    float4 rc = quant_block(c);
    float4 rd = quant_block(d);

    __stcs(&out[i], ra);
    if (i1 < n4) __stcs(&out[i1], rb);
    if (i2 < n4) __stcs(&out[i2], rc);
    if (i3 < n4) __stcs(&out[i3], rd);
}

extern "C" void kernel_launch(void* const* d_in, const int* in_sizes, int n_in,
                              void* d_out, int out_size)
{
    const float4* in  = (const float4*)d_in[0];
    float4*       out = (float4*)d_out;
    int n  = in_sizes[0];        // 4*4096*4096 = 2^26
    int n4 = n >> 2;             // 2^24 float4
    const int threads = 256;

    if ((n4 & 3) == 0 && ((n4 >> 2) % threads) == 0) {
        int q4 = n4 >> 2;        // 2^22 threads, 16384 blocks exactly
        mxint_gelu_exact<<<q4 / threads, threads>>>(in, out, q4);
    } else {
        int q4 = (n4 + 3) >> 2;
        int blocks = (q4 + threads - 1) / threads;
        mxint_gelu_guarded<<<blocks, threads>>>(in, out, n4, q4);
    }
}